// round 7
// baseline (speedup 1.0000x reference)
#include <cuda_runtime.h>
#include <cuda_fp16.h>
#include <cstdint>

#define F_IN 256
#define H1   128
#define H2   64
#define MAXN 100000
#define MAXE 2000000

// Scratch (__device__ globals; allocation-free rule)
__device__ __align__(256) float g_dinv[MAXN];
__device__ __align__(256) float g_h[(size_t)MAXN * H1];    // h1(fp16) -> agg2(fp32)
__device__ __align__(256) float g_agg[(size_t)MAXN * H1];  // hidden(fp16)
__device__ int g_cnt[MAXN];
__device__ int g_incl[MAXN];
__device__ int g_off[MAXN];
__device__ int g_cur[MAXN];
__device__ int g_bsum[256];
__device__ int g_esrc[MAXE];
__device__ int g_is64;

// ---------------------------------------------------------------------------
// Fused: zero cnt + dtype detect (block 0 handles detect).
// int64 LE edge values < 2^31 -> all odd 32-bit words are zero.
__global__ void k_init(const int* __restrict__ ei32, int words, int* cnt, int n) {
    int i = blockIdx.x * blockDim.x + threadIdx.x;
    if (i < n) cnt[i] = 0;
    if (blockIdx.x == 0) {
        __shared__ int anynz;
        if (threadIdx.x == 0) anynz = 0;
        __syncthreads();
        int idx = 1 + 2 * (int)threadIdx.x;
        if (idx < words && ei32[idx] != 0) atomicExch(&anynz, 1);
        __syncthreads();
        if (threadIdx.x == 0) g_is64 = (anynz == 0) ? 1 : 0;
    }
}

__device__ __forceinline__ int edge_at(const void* ei, size_t idx) {
    if (g_is64) return (int)((const long long*)ei)[idx];
    return ((const int*)ei)[idx];
}

__global__ void k_hist(const void* __restrict__ ei, int* cnt, int E, int M) {
    int e = blockIdx.x * blockDim.x + threadIdx.x;
    if (e < E) {
        int d = edge_at(ei, (size_t)E + e);
        if ((unsigned)d < (unsigned)M) atomicAdd(cnt + d, 1);
    }
}

__global__ void k_scan1(const int* __restrict__ cnt, int* incl, int* bsum, int M) {
    __shared__ int sh[1024];
    int i = blockIdx.x * 1024 + threadIdx.x;
    int v = (i < M) ? cnt[i] : 0;
    sh[threadIdx.x] = v;
    __syncthreads();
#pragma unroll
    for (int d = 1; d < 1024; d <<= 1) {
        int t = (threadIdx.x >= d) ? sh[threadIdx.x - d] : 0;
        __syncthreads();
        sh[threadIdx.x] += t;
        __syncthreads();
    }
    if (i < M) incl[i] = sh[threadIdx.x];
    if (threadIdx.x == 1023) bsum[blockIdx.x] = sh[1023];
}

__global__ void k_scan2(int* bsum, int nb) {
    __shared__ int sh[128];
    int t = threadIdx.x;
    int v = (t < nb) ? bsum[t] : 0;
    sh[t] = v;
    __syncthreads();
#pragma unroll
    for (int d = 1; d < 128; d <<= 1) {
        int x = (t >= d) ? sh[t - d] : 0;
        __syncthreads();
        sh[t] += x;
        __syncthreads();
    }
    if (t < nb) bsum[t] = sh[t] - v;
}

// Fused: off/cur from scan pieces + dinv = rsqrt(1 + cnt)
__global__ void k_scan3(const int* __restrict__ incl, const int* __restrict__ cnt,
                        const int* __restrict__ bsum, int* off, int* cur,
                        float* dinv, int M) {
    int i = blockIdx.x * blockDim.x + threadIdx.x;
    if (i < M) {
        int c = cnt[i];
        int o = incl[i] - c + bsum[i >> 10];
        off[i] = o;
        cur[i] = o;
        dinv[i] = rsqrtf(1.0f + (float)c);
    }
}

__global__ void k_fill(const void* __restrict__ ei, int* cur, int* esrc, int E, int M) {
    int e = blockIdx.x * blockDim.x + threadIdx.x;
    if (e < E) {
        int s = edge_at(ei, (size_t)e);
        int d = edge_at(ei, (size_t)E + e);
        if ((unsigned)s < (unsigned)M && (unsigned)d < (unsigned)M) {
            int pos = atomicAdd(cur + d, 1);
            esrc[pos] = s;
        }
    }
}

// ---------------------------------------------------------------------------
// TF32 tensor-core GEMM. BM=128, BN=128, KCHUNK=16, 256 threads.
__device__ __forceinline__ uint32_t f2tf32(float f) {
    uint32_t u;
    asm("cvt.rna.tf32.f32 %0, %1;" : "=r"(u) : "f"(f));
    return u;
}

__device__ __forceinline__ void mma_tf32(float* c, const uint32_t* a,
                                         uint32_t b0, uint32_t b1) {
    asm volatile(
        "mma.sync.aligned.m16n8k8.row.col.f32.tf32.tf32.f32 "
        "{%0,%1,%2,%3}, {%4,%5,%6,%7}, {%8,%9}, {%0,%1,%2,%3};\n"
        : "+f"(c[0]), "+f"(c[1]), "+f"(c[2]), "+f"(c[3])
        : "r"(a[0]), "r"(a[1]), "r"(a[2]), "r"(a[3]), "r"(b0), "r"(b1));
}

template<int KT, bool SPLIT, bool OUTHALF>
__global__ __launch_bounds__(256) void k_gemm_tc(
    const float* __restrict__ A,
    const float* __restrict__ B1, const float* __restrict__ B2,
    const float* __restrict__ bias1, const float* __restrict__ bias2,
    void* __restrict__ outv, int M)
{
    __shared__ uint32_t As[2][128][20];
    __shared__ uint32_t BsT[2][128][20];

    const int tid = threadIdx.x;
    const int lane = tid & 31;
    const int quad = lane >> 2;
    const int kq = lane & 3;
    const int warp = tid >> 5;
    const int wm = warp & 3;
    const int wn = warp >> 2;
    const int brow = blockIdx.x * 128;

    float c[2][8][4];
#pragma unroll
    for (int mt = 0; mt < 2; mt++)
#pragma unroll
        for (int nt = 0; nt < 8; nt++)
#pragma unroll
            for (int i = 0; i < 4; i++) c[mt][nt][i] = 0.0f;

    float4 ra[2], rb[2];

    auto loadG = [&](int k0) {
#pragma unroll
        for (int t = 0; t < 2; t++) {
            int idx = tid + t * 256;
            int row = idx >> 2, kk0 = (idx & 3) * 4;
            int gr = brow + row;
            ra[t] = (gr < M) ? *(const float4*)(A + (size_t)gr * KT + k0 + kk0)
                             : make_float4(0.f, 0.f, 0.f, 0.f);
        }
#pragma unroll
        for (int t = 0; t < 2; t++) {
            int idx = tid + t * 256;
            int k = idx >> 5, c0 = (idx & 31) * 4;
            if (!SPLIT)
                rb[t] = *(const float4*)(B1 + (size_t)(k0 + k) * 128 + c0);
            else if (c0 < 64)
                rb[t] = *(const float4*)(B1 + (size_t)(k0 + k) * 64 + c0);
            else
                rb[t] = *(const float4*)(B2 + (size_t)(k0 + k) * 64 + (c0 - 64));
        }
    };

    auto stage = [&](int buf) {
#pragma unroll
        for (int t = 0; t < 2; t++) {
            int idx = tid + t * 256;
            int row = idx >> 2, kk0 = (idx & 3) * 4;
            uint4 u = make_uint4(f2tf32(ra[t].x), f2tf32(ra[t].y),
                                 f2tf32(ra[t].z), f2tf32(ra[t].w));
            *(uint4*)&As[buf][row][kk0] = u;
        }
#pragma unroll
        for (int t = 0; t < 2; t++) {
            int idx = tid + t * 256;
            int k = idx >> 5, c0 = (idx & 31) * 4;
            BsT[buf][c0 + 0][k] = f2tf32(rb[t].x);
            BsT[buf][c0 + 1][k] = f2tf32(rb[t].y);
            BsT[buf][c0 + 2][k] = f2tf32(rb[t].z);
            BsT[buf][c0 + 3][k] = f2tf32(rb[t].w);
        }
    };

    const int NC = KT / 16;
    loadG(0);
    stage(0);
    __syncthreads();

    for (int ch = 0; ch < NC; ch++) {
        int buf = ch & 1;
        if (ch + 1 < NC) loadG((ch + 1) * 16);
#pragma unroll
        for (int ks = 0; ks < 2; ks++) {
            uint32_t a[2][4];
#pragma unroll
            for (int mt = 0; mt < 2; mt++) {
                int r = wm * 32 + mt * 16 + quad;
                a[mt][0] = As[buf][r][ks * 8 + kq];
                a[mt][1] = As[buf][r + 8][ks * 8 + kq];
                a[mt][2] = As[buf][r][ks * 8 + kq + 4];
                a[mt][3] = As[buf][r + 8][ks * 8 + kq + 4];
            }
#pragma unroll
            for (int nt = 0; nt < 8; nt++) {
                int cb = wn * 64 + nt * 8 + quad;
                uint32_t b0 = BsT[buf][cb][ks * 8 + kq];
                uint32_t b1 = BsT[buf][cb][ks * 8 + kq + 4];
                mma_tf32(c[0][nt], a[0], b0, b1);
                mma_tf32(c[1][nt], a[1], b0, b1);
            }
        }
        if (ch + 1 < NC) stage(buf ^ 1);
        __syncthreads();
    }

#pragma unroll
    for (int mt = 0; mt < 2; mt++) {
#pragma unroll
        for (int nt = 0; nt < 8; nt++) {
            int r0 = brow + wm * 32 + mt * 16 + quad;
            int col = wn * 64 + nt * 8 + kq * 2;
            float2 lo = make_float2(c[mt][nt][0], c[mt][nt][1]);
            float2 hi = make_float2(c[mt][nt][2], c[mt][nt][3]);
            if (OUTHALF) {
                __half* out16 = (__half*)outv;
                if (r0 < M)
                    *(__half2*)(out16 + (size_t)r0 * 128 + col) = __float22half2_rn(lo);
                if (r0 + 8 < M)
                    *(__half2*)(out16 + (size_t)(r0 + 8) * 128 + col) = __float22half2_rn(hi);
            } else if (!SPLIT) {
                float* out = (float*)outv;
                if (r0 < M)     *(float2*)(out + (size_t)r0 * 128 + col) = lo;
                if (r0 + 8 < M) *(float2*)(out + (size_t)(r0 + 8) * 128 + col) = hi;
            } else {
                float* out = (float*)outv;
                const float* bs = wn ? bias2 : bias1;
                int chn = col - wn * 64;
                float bx = bs[chn], by = bs[chn + 1];
                size_t base = wn ? (size_t)M * 64 : 0;
                lo.x += bx; lo.y += by; hi.x += bx; hi.y += by;
                if (r0 < M)     *(float2*)(out + base + (size_t)r0 * 64 + chn) = lo;
                if (r0 + 8 < M) *(float2*)(out + base + (size_t)(r0 + 8) * 64 + chn) = hi;
            }
        }
    }
}

// ---------------------------------------------------------------------------
// CSR aggregation over fp16 features. One warp per dst node; 4 halves/lane.
// Inner loop manually 4x unrolled: 4 independent gathers in flight (MLP=4).
template<bool RELU, bool OUT_HALF>
__global__ __launch_bounds__(256) void k_agg(
    const int* __restrict__ esrc, const int* __restrict__ off,
    const int* __restrict__ cnt, const float* __restrict__ dinv,
    const float* __restrict__ bias,
    const __half* __restrict__ Hin, void* __restrict__ Houtv, int M)
{
    int node = (blockIdx.x * blockDim.x + threadIdx.x) >> 5;
    int lane = threadIdx.x & 31;
    if (node >= M) return;
    float di = dinv[node];
    float d2 = di * di;

    const __half* selfrow = Hin + (size_t)node * 128 + lane * 4;
    uint2 raw = *(const uint2*)selfrow;
    float2 f0 = __half22float2(*(__half2*)&raw.x);
    float2 f1 = __half22float2(*(__half2*)&raw.y);
    float a0 = f0.x * d2, a1 = f0.y * d2, a2 = f1.x * d2, a3 = f1.y * d2;

    int o = off[node], c = cnt[node];
    for (int base = 0; base < c; base += 32) {
        int rem = c - base;
        int lim = rem < 32 ? rem : 32;
        int sv = 0; float dv = 0.f;
        if (lane < lim) { sv = esrc[o + base + lane]; dv = dinv[sv]; }

        int j = 0;
        for (; j + 4 <= lim; j += 4) {
            int s0 = __shfl_sync(0xffffffffu, sv, j);
            int s1 = __shfl_sync(0xffffffffu, sv, j + 1);
            int s2 = __shfl_sync(0xffffffffu, sv, j + 2);
            int s3 = __shfl_sync(0xffffffffu, sv, j + 3);
            float c0 = __shfl_sync(0xffffffffu, dv, j)     * di;
            float c1 = __shfl_sync(0xffffffffu, dv, j + 1) * di;
            float c2 = __shfl_sync(0xffffffffu, dv, j + 2) * di;
            float c3 = __shfl_sync(0xffffffffu, dv, j + 3) * di;
            uint2 r0 = *(const uint2*)(Hin + (size_t)s0 * 128 + lane * 4);
            uint2 r1 = *(const uint2*)(Hin + (size_t)s1 * 128 + lane * 4);
            uint2 r2 = *(const uint2*)(Hin + (size_t)s2 * 128 + lane * 4);
            uint2 r3 = *(const uint2*)(Hin + (size_t)s3 * 128 + lane * 4);
            {
                float2 v0 = __half22float2(*(__half2*)&r0.x);
                float2 v1 = __half22float2(*(__half2*)&r0.y);
                a0 = fmaf(v0.x, c0, a0); a1 = fmaf(v0.y, c0, a1);
                a2 = fmaf(v1.x, c0, a2); a3 = fmaf(v1.y, c0, a3);
            }
            {
                float2 v0 = __half22float2(*(__half2*)&r1.x);
                float2 v1 = __half22float2(*(__half2*)&r1.y);
                a0 = fmaf(v0.x, c1, a0); a1 = fmaf(v0.y, c1, a1);
                a2 = fmaf(v1.x, c1, a2); a3 = fmaf(v1.y, c1, a3);
            }
            {
                float2 v0 = __half22float2(*(__half2*)&r2.x);
                float2 v1 = __half22float2(*(__half2*)&r2.y);
                a0 = fmaf(v0.x, c2, a0); a1 = fmaf(v0.y, c2, a1);
                a2 = fmaf(v1.x, c2, a2); a3 = fmaf(v1.y, c2, a3);
            }
            {
                float2 v0 = __half22float2(*(__half2*)&r3.x);
                float2 v1 = __half22float2(*(__half2*)&r3.y);
                a0 = fmaf(v0.x, c3, a0); a1 = fmaf(v0.y, c3, a1);
                a2 = fmaf(v1.x, c3, a2); a3 = fmaf(v1.y, c3, a3);
            }
        }
        for (; j < lim; j++) {
            int s = __shfl_sync(0xffffffffu, sv, j);
            float cf = __shfl_sync(0xffffffffu, dv, j) * di;
            uint2 r = *(const uint2*)(Hin + (size_t)s * 128 + lane * 4);
            float2 v0 = __half22float2(*(__half2*)&r.x);
            float2 v1 = __half22float2(*(__half2*)&r.y);
            a0 = fmaf(v0.x, cf, a0); a1 = fmaf(v0.y, cf, a1);
            a2 = fmaf(v1.x, cf, a2); a3 = fmaf(v1.y, cf, a3);
        }
    }
    if (RELU) {
        float4 b4 = *(const float4*)(bias + lane * 4);
        a0 = fmaxf(a0 + b4.x, 0.f);
        a1 = fmaxf(a1 + b4.y, 0.f);
        a2 = fmaxf(a2 + b4.z, 0.f);
        a3 = fmaxf(a3 + b4.w, 0.f);
    }
    if (OUT_HALF) {
        __half* out16 = (__half*)Houtv;
        uint2 w;
        *(__half2*)&w.x = __float22half2_rn(make_float2(a0, a1));
        *(__half2*)&w.y = __float22half2_rn(make_float2(a2, a3));
        *(uint2*)(out16 + (size_t)node * 128 + lane * 4) = w;
    } else {
        float* out = (float*)Houtv;
        *(float4*)(out + (size_t)node * 128 + lane * 4) = make_float4(a0, a1, a2, a3);
    }
}

// ---------------------------------------------------------------------------
extern "C" void kernel_launch(void* const* d_in, const int* in_sizes, int n_in,
                              void* d_out, int out_size)
{
    const float *x = nullptr, *w1 = nullptr, *b1 = nullptr;
    const float *w2 = nullptr, *b2 = nullptr, *w3 = nullptr, *b3 = nullptr;
    const void* ei = nullptr;
    int M = 0, E = 0;

    for (int i = 0; i < n_in; i++) {
        int sz = in_sizes[i];
        if (sz == F_IN * H1) {
            w1 = (const float*)d_in[i];
        } else if (sz == H1) {
            b1 = (const float*)d_in[i];
        } else if (sz == H1 * H2) {
            if (!w2) w2 = (const float*)d_in[i];
            else     w3 = (const float*)d_in[i];
        } else if (sz == H2) {
            if (!b2) b2 = (const float*)d_in[i];
            else     b3 = (const float*)d_in[i];
        } else if (sz < 8000000) {
            ei = d_in[i];
            E = sz / 2;
        } else {
            x = (const float*)d_in[i];
            M = sz / F_IN;
        }
    }

    float *dinv, *H, *AGG;
    int *cnt, *incl, *off, *cur, *bsum, *esrc;
    cudaGetSymbolAddress((void**)&dinv, g_dinv);
    cudaGetSymbolAddress((void**)&H,    g_h);
    cudaGetSymbolAddress((void**)&AGG,  g_agg);
    cudaGetSymbolAddress((void**)&cnt,  g_cnt);
    cudaGetSymbolAddress((void**)&incl, g_incl);
    cudaGetSymbolAddress((void**)&off,  g_off);
    cudaGetSymbolAddress((void**)&cur,  g_cur);
    cudaGetSymbolAddress((void**)&bsum, g_bsum);
    cudaGetSymbolAddress((void**)&esrc, g_esrc);

    float* out = (float*)d_out;
    __half* H16   = (__half*)H;     // h1 in fp16 (g_h)
    __half* HID16 = (__half*)AGG;   // hidden in fp16 (g_agg)

    int nb1024 = (M + 1023) / 1024;

    k_init<<<(M + 255) / 256, 256>>>((const int*)ei, 2 * E, cnt, M);
    k_hist<<<(E + 255) / 256, 256>>>(ei, cnt, E, M);
    k_scan1<<<nb1024, 1024>>>(cnt, incl, bsum, M);
    k_scan2<<<1, 128>>>(bsum, nb1024);
    k_scan3<<<(M + 255) / 256, 256>>>(incl, cnt, bsum, off, cur, dinv, M);
    k_fill<<<(E + 255) / 256, 256>>>(ei, cur, esrc, E, M);

    int gblocks = (M + 127) / 128;
    int ablocks = (M * 32 + 255) / 256;

    // layer 1: x@w1 -> H16 (fp16); agg + b1 + relu -> HID16 (fp16)
    k_gemm_tc<F_IN, false, true><<<gblocks, 256>>>(x, w1, nullptr, nullptr, nullptr, H16, M);
    k_agg<true, true><<<ablocks, 256>>>(esrc, off, cnt, dinv, b1, H16, HID16, M);
    // layer 2 aggregation: HID16 -> H (fp32, GEMM2 input)
    k_agg<false, false><<<ablocks, 256>>>(esrc, off, cnt, dinv, nullptr, HID16, H, M);
    // fused output GEMM: H @ [w2|w3] + [b2|b3] -> (mu, logvar)
    k_gemm_tc<H1, true, false><<<gblocks, 256>>>(H, w2, w3, b2, b3, out, M);
    (void)out_size;
}

// round 8
// speedup vs baseline: 1.1097x; 1.1097x over previous
#include <cuda_runtime.h>
#include <cuda_fp16.h>
#include <cstdint>

#define F_IN 256
#define H1   128
#define H2   64
#define MAXN 100000
#define MAXE 2000000

// Scratch (__device__ globals; allocation-free rule)
__device__ __align__(256) float g_dinv[MAXN];
__device__ __align__(256) float g_h[(size_t)MAXN * H1];    // h1(fp16) -> agg2(fp32)
__device__ __align__(256) float g_agg[(size_t)MAXN * H1];  // hidden(fp16)
__device__ int g_cnt[MAXN];
__device__ int g_incl[MAXN];
__device__ int g_off[MAXN];
__device__ int g_cur[MAXN];
__device__ int g_bsum[256];
__device__ int g_esrc[MAXE];
__device__ int g_is64;

// ---------------------------------------------------------------------------
// Fused: zero cnt + dtype detect (block 0).
__global__ void k_init(const int* __restrict__ ei32, int words, int* cnt, int n) {
    int i = blockIdx.x * blockDim.x + threadIdx.x;
    if (i < n) cnt[i] = 0;
    if (blockIdx.x == 0) {
        __shared__ int anynz;
        if (threadIdx.x == 0) anynz = 0;
        __syncthreads();
        int idx = 1 + 2 * (int)threadIdx.x;
        if (idx < words && ei32[idx] != 0) atomicExch(&anynz, 1);
        __syncthreads();
        if (threadIdx.x == 0) g_is64 = (anynz == 0) ? 1 : 0;
    }
}

__device__ __forceinline__ int edge_at(const void* ei, size_t idx) {
    if (g_is64) return (int)((const long long*)ei)[idx];
    return ((const int*)ei)[idx];
}

__global__ void k_hist(const void* __restrict__ ei, int* cnt, int E, int M) {
    int e = blockIdx.x * blockDim.x + threadIdx.x;
    if (e < E) {
        int d = edge_at(ei, (size_t)E + e);
        if ((unsigned)d < (unsigned)M) atomicAdd(cnt + d, 1);
    }
}

__global__ void k_scan1(const int* __restrict__ cnt, int* incl, int* bsum, int M) {
    __shared__ int sh[1024];
    int i = blockIdx.x * 1024 + threadIdx.x;
    int v = (i < M) ? cnt[i] : 0;
    sh[threadIdx.x] = v;
    __syncthreads();
#pragma unroll
    for (int d = 1; d < 1024; d <<= 1) {
        int t = (threadIdx.x >= d) ? sh[threadIdx.x - d] : 0;
        __syncthreads();
        sh[threadIdx.x] += t;
        __syncthreads();
    }
    if (i < M) incl[i] = sh[threadIdx.x];
    if (threadIdx.x == 1023) bsum[blockIdx.x] = sh[1023];
}

__global__ void k_scan2(int* bsum, int nb) {
    __shared__ int sh[128];
    int t = threadIdx.x;
    int v = (t < nb) ? bsum[t] : 0;
    sh[t] = v;
    __syncthreads();
#pragma unroll
    for (int d = 1; d < 128; d <<= 1) {
        int x = (t >= d) ? sh[t - d] : 0;
        __syncthreads();
        sh[t] += x;
        __syncthreads();
    }
    if (t < nb) bsum[t] = sh[t] - v;
}

// Fused: off/cur + dinv = rsqrt(1 + cnt)
__global__ void k_scan3(const int* __restrict__ incl, const int* __restrict__ cnt,
                        const int* __restrict__ bsum, int* off, int* cur,
                        float* dinv, int M) {
    int i = blockIdx.x * blockDim.x + threadIdx.x;
    if (i < M) {
        int c = cnt[i];
        int o = incl[i] - c + bsum[i >> 10];
        off[i] = o;
        cur[i] = o;
        dinv[i] = rsqrtf(1.0f + (float)c);
    }
}

__global__ void k_fill(const void* __restrict__ ei, int* cur, int* esrc, int E, int M) {
    int e = blockIdx.x * blockDim.x + threadIdx.x;
    if (e < E) {
        int s = edge_at(ei, (size_t)e);
        int d = edge_at(ei, (size_t)E + e);
        if ((unsigned)s < (unsigned)M && (unsigned)d < (unsigned)M) {
            int pos = atomicAdd(cur + d, 1);
            esrc[pos] = s;
        }
    }
}

// ---------------------------------------------------------------------------
// TF32 tensor-core GEMM (unchanged from R6).
__device__ __forceinline__ uint32_t f2tf32(float f) {
    uint32_t u;
    asm("cvt.rna.tf32.f32 %0, %1;" : "=r"(u) : "f"(f));
    return u;
}

__device__ __forceinline__ void mma_tf32(float* c, const uint32_t* a,
                                         uint32_t b0, uint32_t b1) {
    asm volatile(
        "mma.sync.aligned.m16n8k8.row.col.f32.tf32.tf32.f32 "
        "{%0,%1,%2,%3}, {%4,%5,%6,%7}, {%8,%9}, {%0,%1,%2,%3};\n"
        : "+f"(c[0]), "+f"(c[1]), "+f"(c[2]), "+f"(c[3])
        : "r"(a[0]), "r"(a[1]), "r"(a[2]), "r"(a[3]), "r"(b0), "r"(b1));
}

template<int KT, bool SPLIT, bool OUTHALF>
__global__ __launch_bounds__(256) void k_gemm_tc(
    const float* __restrict__ A,
    const float* __restrict__ B1, const float* __restrict__ B2,
    const float* __restrict__ bias1, const float* __restrict__ bias2,
    void* __restrict__ outv, int M)
{
    __shared__ uint32_t As[2][128][20];
    __shared__ uint32_t BsT[2][128][20];

    const int tid = threadIdx.x;
    const int lane = tid & 31;
    const int quad = lane >> 2;
    const int kq = lane & 3;
    const int warp = tid >> 5;
    const int wm = warp & 3;
    const int wn = warp >> 2;
    const int brow = blockIdx.x * 128;

    float c[2][8][4];
#pragma unroll
    for (int mt = 0; mt < 2; mt++)
#pragma unroll
        for (int nt = 0; nt < 8; nt++)
#pragma unroll
            for (int i = 0; i < 4; i++) c[mt][nt][i] = 0.0f;

    float4 ra[2], rb[2];

    auto loadG = [&](int k0) {
#pragma unroll
        for (int t = 0; t < 2; t++) {
            int idx = tid + t * 256;
            int row = idx >> 2, kk0 = (idx & 3) * 4;
            int gr = brow + row;
            ra[t] = (gr < M) ? *(const float4*)(A + (size_t)gr * KT + k0 + kk0)
                             : make_float4(0.f, 0.f, 0.f, 0.f);
        }
#pragma unroll
        for (int t = 0; t < 2; t++) {
            int idx = tid + t * 256;
            int k = idx >> 5, c0 = (idx & 31) * 4;
            if (!SPLIT)
                rb[t] = *(const float4*)(B1 + (size_t)(k0 + k) * 128 + c0);
            else if (c0 < 64)
                rb[t] = *(const float4*)(B1 + (size_t)(k0 + k) * 64 + c0);
            else
                rb[t] = *(const float4*)(B2 + (size_t)(k0 + k) * 64 + (c0 - 64));
        }
    };

    auto stage = [&](int buf) {
#pragma unroll
        for (int t = 0; t < 2; t++) {
            int idx = tid + t * 256;
            int row = idx >> 2, kk0 = (idx & 3) * 4;
            uint4 u = make_uint4(f2tf32(ra[t].x), f2tf32(ra[t].y),
                                 f2tf32(ra[t].z), f2tf32(ra[t].w));
            *(uint4*)&As[buf][row][kk0] = u;
        }
#pragma unroll
        for (int t = 0; t < 2; t++) {
            int idx = tid + t * 256;
            int k = idx >> 5, c0 = (idx & 31) * 4;
            BsT[buf][c0 + 0][k] = f2tf32(rb[t].x);
            BsT[buf][c0 + 1][k] = f2tf32(rb[t].y);
            BsT[buf][c0 + 2][k] = f2tf32(rb[t].z);
            BsT[buf][c0 + 3][k] = f2tf32(rb[t].w);
        }
    };

    const int NC = KT / 16;
    loadG(0);
    stage(0);
    __syncthreads();

    for (int ch = 0; ch < NC; ch++) {
        int buf = ch & 1;
        if (ch + 1 < NC) loadG((ch + 1) * 16);
#pragma unroll
        for (int ks = 0; ks < 2; ks++) {
            uint32_t a[2][4];
#pragma unroll
            for (int mt = 0; mt < 2; mt++) {
                int r = wm * 32 + mt * 16 + quad;
                a[mt][0] = As[buf][r][ks * 8 + kq];
                a[mt][1] = As[buf][r + 8][ks * 8 + kq];
                a[mt][2] = As[buf][r][ks * 8 + kq + 4];
                a[mt][3] = As[buf][r + 8][ks * 8 + kq + 4];
            }
#pragma unroll
            for (int nt = 0; nt < 8; nt++) {
                int cb = wn * 64 + nt * 8 + quad;
                uint32_t b0 = BsT[buf][cb][ks * 8 + kq];
                uint32_t b1 = BsT[buf][cb][ks * 8 + kq + 4];
                mma_tf32(c[0][nt], a[0], b0, b1);
                mma_tf32(c[1][nt], a[1], b0, b1);
            }
        }
        if (ch + 1 < NC) stage(buf ^ 1);
        __syncthreads();
    }

#pragma unroll
    for (int mt = 0; mt < 2; mt++) {
#pragma unroll
        for (int nt = 0; nt < 8; nt++) {
            int r0 = brow + wm * 32 + mt * 16 + quad;
            int col = wn * 64 + nt * 8 + kq * 2;
            float2 lo = make_float2(c[mt][nt][0], c[mt][nt][1]);
            float2 hi = make_float2(c[mt][nt][2], c[mt][nt][3]);
            if (OUTHALF) {
                __half* out16 = (__half*)outv;
                if (r0 < M)
                    *(__half2*)(out16 + (size_t)r0 * 128 + col) = __float22half2_rn(lo);
                if (r0 + 8 < M)
                    *(__half2*)(out16 + (size_t)(r0 + 8) * 128 + col) = __float22half2_rn(hi);
            } else if (!SPLIT) {
                float* out = (float*)outv;
                if (r0 < M)     *(float2*)(out + (size_t)r0 * 128 + col) = lo;
                if (r0 + 8 < M) *(float2*)(out + (size_t)(r0 + 8) * 128 + col) = hi;
            } else {
                float* out = (float*)outv;
                const float* bs = wn ? bias2 : bias1;
                int chn = col - wn * 64;
                float bx = bs[chn], by = bs[chn + 1];
                size_t base = wn ? (size_t)M * 64 : 0;
                lo.x += bx; lo.y += by; hi.x += bx; hi.y += by;
                if (r0 < M)     *(float2*)(out + base + (size_t)r0 * 64 + chn) = lo;
                if (r0 + 8 < M) *(float2*)(out + base + (size_t)(r0 + 8) * 64 + chn) = hi;
            }
        }
    }
}

// ---------------------------------------------------------------------------
// CSR aggregation: HALF-WARP (16 lanes) per dst node, 2 nodes per warp.
// Each lane covers 8 channels via one uint4 (16B) load per gathered row.
template<bool RELU, bool OUT_HALF>
__global__ __launch_bounds__(256) void k_agg(
    const int* __restrict__ esrc, const int* __restrict__ off,
    const int* __restrict__ cnt, const float* __restrict__ dinv,
    const float* __restrict__ bias,
    const __half* __restrict__ Hin, void* __restrict__ Houtv, int M)
{
    int node = (blockIdx.x * blockDim.x + threadIdx.x) >> 4;
    int lane = threadIdx.x & 15;
    unsigned mask = 0xFFFFu << (threadIdx.x & 16);   // this half-warp's lanes
    if (node >= M) return;

    float di = dinv[node];
    float d2 = di * di;

    // self row: 8 halves per lane
    uint4 raw = *((const uint4*)(Hin + (size_t)node * 128) + lane);
    float2 s0 = __half22float2(*(__half2*)&raw.x);
    float2 s1 = __half22float2(*(__half2*)&raw.y);
    float2 s2 = __half22float2(*(__half2*)&raw.z);
    float2 s3 = __half22float2(*(__half2*)&raw.w);
    float a0 = s0.x * d2, a1 = s0.y * d2, a2 = s1.x * d2, a3 = s1.y * d2;
    float a4 = s2.x * d2, a5 = s2.y * d2, a6 = s3.x * d2, a7 = s3.y * d2;

    int o = off[node], c = cnt[node];
    for (int base = 0; base < c; base += 16) {
        int rem = c - base;
        int lim = rem < 16 ? rem : 16;
        int sv = 0; float dv = 0.f;
        if (lane < lim) { sv = esrc[o + base + lane]; dv = dinv[sv]; }
        for (int j = 0; j < lim; j++) {
            int s = __shfl_sync(mask, sv, j, 16);
            float cf = __shfl_sync(mask, dv, j, 16) * di;
            uint4 r = *((const uint4*)(Hin + (size_t)s * 128) + lane);
            float2 v0 = __half22float2(*(__half2*)&r.x);
            float2 v1 = __half22float2(*(__half2*)&r.y);
            float2 v2 = __half22float2(*(__half2*)&r.z);
            float2 v3 = __half22float2(*(__half2*)&r.w);
            a0 = fmaf(v0.x, cf, a0); a1 = fmaf(v0.y, cf, a1);
            a2 = fmaf(v1.x, cf, a2); a3 = fmaf(v1.y, cf, a3);
            a4 = fmaf(v2.x, cf, a4); a5 = fmaf(v2.y, cf, a5);
            a6 = fmaf(v3.x, cf, a6); a7 = fmaf(v3.y, cf, a7);
        }
    }
    if (RELU) {
        float4 b0 = *((const float4*)bias + lane * 2);
        float4 b1 = *((const float4*)bias + lane * 2 + 1);
        a0 = fmaxf(a0 + b0.x, 0.f); a1 = fmaxf(a1 + b0.y, 0.f);
        a2 = fmaxf(a2 + b0.z, 0.f); a3 = fmaxf(a3 + b0.w, 0.f);
        a4 = fmaxf(a4 + b1.x, 0.f); a5 = fmaxf(a5 + b1.y, 0.f);
        a6 = fmaxf(a6 + b1.z, 0.f); a7 = fmaxf(a7 + b1.w, 0.f);
    }
    if (OUT_HALF) {
        __half* out16 = (__half*)Houtv;
        uint4 w;
        *(__half2*)&w.x = __float22half2_rn(make_float2(a0, a1));
        *(__half2*)&w.y = __float22half2_rn(make_float2(a2, a3));
        *(__half2*)&w.z = __float22half2_rn(make_float2(a4, a5));
        *(__half2*)&w.w = __float22half2_rn(make_float2(a6, a7));
        *((uint4*)(out16 + (size_t)node * 128) + lane) = w;
    } else {
        float* out = (float*)Houtv;
        float4* p = (float4*)(out + (size_t)node * 128) + lane * 2;
        p[0] = make_float4(a0, a1, a2, a3);
        p[1] = make_float4(a4, a5, a6, a7);
    }
}

// ---------------------------------------------------------------------------
extern "C" void kernel_launch(void* const* d_in, const int* in_sizes, int n_in,
                              void* d_out, int out_size)
{
    const float *x = nullptr, *w1 = nullptr, *b1 = nullptr;
    const float *w2 = nullptr, *b2 = nullptr, *w3 = nullptr, *b3 = nullptr;
    const void* ei = nullptr;
    int M = 0, E = 0;

    for (int i = 0; i < n_in; i++) {
        int sz = in_sizes[i];
        if (sz == F_IN * H1) {
            w1 = (const float*)d_in[i];
        } else if (sz == H1) {
            b1 = (const float*)d_in[i];
        } else if (sz == H1 * H2) {
            if (!w2) w2 = (const float*)d_in[i];
            else     w3 = (const float*)d_in[i];
        } else if (sz == H2) {
            if (!b2) b2 = (const float*)d_in[i];
            else     b3 = (const float*)d_in[i];
        } else if (sz < 8000000) {
            ei = d_in[i];
            E = sz / 2;
        } else {
            x = (const float*)d_in[i];
            M = sz / F_IN;
        }
    }

    float *dinv, *H, *AGG;
    int *cnt, *incl, *off, *cur, *bsum, *esrc;
    cudaGetSymbolAddress((void**)&dinv, g_dinv);
    cudaGetSymbolAddress((void**)&H,    g_h);
    cudaGetSymbolAddress((void**)&AGG,  g_agg);
    cudaGetSymbolAddress((void**)&cnt,  g_cnt);
    cudaGetSymbolAddress((void**)&incl, g_incl);
    cudaGetSymbolAddress((void**)&off,  g_off);
    cudaGetSymbolAddress((void**)&cur,  g_cur);
    cudaGetSymbolAddress((void**)&bsum, g_bsum);
    cudaGetSymbolAddress((void**)&esrc, g_esrc);

    float* out = (float*)d_out;
    __half* H16   = (__half*)H;     // h1 in fp16 (g_h)
    __half* HID16 = (__half*)AGG;   // hidden in fp16 (g_agg)

    int nb1024 = (M + 1023) / 1024;

    k_init<<<(M + 255) / 256, 256>>>((const int*)ei, 2 * E, cnt, M);
    k_hist<<<(E + 255) / 256, 256>>>(ei, cnt, E, M);
    k_scan1<<<nb1024, 1024>>>(cnt, incl, bsum, M);
    k_scan2<<<1, 128>>>(bsum, nb1024);
    k_scan3<<<(M + 255) / 256, 256>>>(incl, cnt, bsum, off, cur, dinv, M);
    k_fill<<<(E + 255) / 256, 256>>>(ei, cur, esrc, E, M);

    int gblocks = (M + 127) / 128;
    int ablocks = (M * 16 + 255) / 256;   // half-warp per node

    // layer 1: x@w1 -> H16 (fp16); agg + b1 + relu -> HID16 (fp16)
    k_gemm_tc<F_IN, false, true><<<gblocks, 256>>>(x, w1, nullptr, nullptr, nullptr, H16, M);
    k_agg<true, true><<<ablocks, 256>>>(esrc, off, cnt, dinv, b1, H16, HID16, M);
    // layer 2 aggregation: HID16 -> H (fp32, GEMM2 input)
    k_agg<false, false><<<ablocks, 256>>>(esrc, off, cnt, dinv, nullptr, HID16, H, M);
    // fused output GEMM: H @ [w2|w3] + [b2|b3] -> (mu, logvar)
    k_gemm_tc<H1, true, false><<<gblocks, 256>>>(H, w2, w3, b2, b3, out, M);
    (void)out_size;
}

// round 9
// speedup vs baseline: 1.1437x; 1.0306x over previous
#include <cuda_runtime.h>
#include <cuda_fp16.h>
#include <cstdint>

#define F_IN 256
#define H1   128
#define H2   64
#define MAXN 100000
#define MAXE 2000000

// Scratch (__device__ globals; allocation-free rule)
__device__ __align__(256) float g_dinv[MAXN];
__device__ __align__(256) float g_h[(size_t)MAXN * H1];    // h1(fp16) -> agg2(fp16)
__device__ __align__(256) float g_agg[(size_t)MAXN * H1];  // hidden(fp16)
__device__ int g_cnt[MAXN];
__device__ int g_off[MAXN];
__device__ int g_cur[MAXN];
__device__ int g_esrc[MAXE];
__device__ int g_total;
__device__ int g_is64;

// ---------------------------------------------------------------------------
// Fused: zero cnt + total + dtype detect (block 0).
__global__ void k_init(const int* __restrict__ ei32, int words, int* cnt, int n) {
    int i = blockIdx.x * blockDim.x + threadIdx.x;
    if (i < n) cnt[i] = 0;
    if (blockIdx.x == 0) {
        __shared__ int anynz;
        if (threadIdx.x == 0) { anynz = 0; g_total = 0; }
        __syncthreads();
        int idx = 1 + 2 * (int)threadIdx.x;
        if (idx < words && ei32[idx] != 0) atomicExch(&anynz, 1);
        __syncthreads();
        if (threadIdx.x == 0) g_is64 = (anynz == 0) ? 1 : 0;
    }
}

// 4-byte edge read: for int64 LE with values < 2^31 the low word is the value.
__device__ __forceinline__ int edge_at(const void* ei, size_t idx) {
    const int* w = (const int*)ei;
    return g_is64 ? w[2 * idx] : w[idx];
}

__global__ void k_hist(const void* __restrict__ ei, int* cnt, int E, int M) {
    int e = blockIdx.x * blockDim.x + threadIdx.x;
    if (e < E) {
        int d = edge_at(ei, (size_t)E + e);
        if ((unsigned)d < (unsigned)M) atomicAdd(cnt + d, 1);
    }
}

// Segment offsets via atomic bump (order-free; segments disjoint) + dinv.
__global__ void k_off(const int* __restrict__ cnt, int* off, int* cur,
                      float* dinv, int M) {
    int i = blockIdx.x * blockDim.x + threadIdx.x;
    if (i < M) {
        int c = cnt[i];
        int o = atomicAdd(&g_total, c);
        off[i] = o;
        cur[i] = o;
        dinv[i] = rsqrtf(1.0f + (float)c);
    }
}

__global__ void k_fill(const void* __restrict__ ei, int* cur, int* esrc, int E, int M) {
    int e = blockIdx.x * blockDim.x + threadIdx.x;
    if (e < E) {
        int s = edge_at(ei, (size_t)e);
        int d = edge_at(ei, (size_t)E + e);
        if ((unsigned)s < (unsigned)M && (unsigned)d < (unsigned)M) {
            int pos = atomicAdd(cur + d, 1);
            esrc[pos] = s;
        }
    }
}

// ---------------------------------------------------------------------------
// TF32 tensor-core GEMM. BM=128, BN=128, KCHUNK=16, 256 threads.
// AHALF: A operand is fp16. OUTHALF: fp16 output. SPLIT: [B1|B2]+bias, split store.
__device__ __forceinline__ uint32_t f2tf32(float f) {
    uint32_t u;
    asm("cvt.rna.tf32.f32 %0, %1;" : "=r"(u) : "f"(f));
    return u;
}

__device__ __forceinline__ void mma_tf32(float* c, const uint32_t* a,
                                         uint32_t b0, uint32_t b1) {
    asm volatile(
        "mma.sync.aligned.m16n8k8.row.col.f32.tf32.tf32.f32 "
        "{%0,%1,%2,%3}, {%4,%5,%6,%7}, {%8,%9}, {%0,%1,%2,%3};\n"
        : "+f"(c[0]), "+f"(c[1]), "+f"(c[2]), "+f"(c[3])
        : "r"(a[0]), "r"(a[1]), "r"(a[2]), "r"(a[3]), "r"(b0), "r"(b1));
}

template<int KT, bool SPLIT, bool OUTHALF, bool AHALF>
__global__ __launch_bounds__(256) void k_gemm_tc(
    const void* __restrict__ Av,
    const float* __restrict__ B1, const float* __restrict__ B2,
    const float* __restrict__ bias1, const float* __restrict__ bias2,
    void* __restrict__ outv, int M)
{
    __shared__ uint32_t As[2][128][20];
    __shared__ uint32_t BsT[2][128][20];

    const int tid = threadIdx.x;
    const int lane = tid & 31;
    const int quad = lane >> 2;
    const int kq = lane & 3;
    const int warp = tid >> 5;
    const int wm = warp & 3;
    const int wn = warp >> 2;
    const int brow = blockIdx.x * 128;

    float c[2][8][4];
#pragma unroll
    for (int mt = 0; mt < 2; mt++)
#pragma unroll
        for (int nt = 0; nt < 8; nt++)
#pragma unroll
            for (int i = 0; i < 4; i++) c[mt][nt][i] = 0.0f;

    float4 ra[2], rb[2];

    auto loadG = [&](int k0) {
#pragma unroll
        for (int t = 0; t < 2; t++) {
            int idx = tid + t * 256;
            int row = idx >> 2, kk0 = (idx & 3) * 4;
            int gr = brow + row;
            if (gr >= M) { ra[t] = make_float4(0.f, 0.f, 0.f, 0.f); continue; }
            if (AHALF) {
                const __half* A16 = (const __half*)Av;
                uint2 h = *(const uint2*)(A16 + (size_t)gr * KT + k0 + kk0);
                float2 p0 = __half22float2(*(__half2*)&h.x);
                float2 p1 = __half22float2(*(__half2*)&h.y);
                ra[t] = make_float4(p0.x, p0.y, p1.x, p1.y);
            } else {
                const float* A = (const float*)Av;
                ra[t] = *(const float4*)(A + (size_t)gr * KT + k0 + kk0);
            }
        }
#pragma unroll
        for (int t = 0; t < 2; t++) {
            int idx = tid + t * 256;
            int k = idx >> 5, c0 = (idx & 31) * 4;
            if (!SPLIT)
                rb[t] = *(const float4*)(B1 + (size_t)(k0 + k) * 128 + c0);
            else if (c0 < 64)
                rb[t] = *(const float4*)(B1 + (size_t)(k0 + k) * 64 + c0);
            else
                rb[t] = *(const float4*)(B2 + (size_t)(k0 + k) * 64 + (c0 - 64));
        }
    };

    auto stage = [&](int buf) {
#pragma unroll
        for (int t = 0; t < 2; t++) {
            int idx = tid + t * 256;
            int row = idx >> 2, kk0 = (idx & 3) * 4;
            uint4 u = make_uint4(f2tf32(ra[t].x), f2tf32(ra[t].y),
                                 f2tf32(ra[t].z), f2tf32(ra[t].w));
            *(uint4*)&As[buf][row][kk0] = u;
        }
#pragma unroll
        for (int t = 0; t < 2; t++) {
            int idx = tid + t * 256;
            int k = idx >> 5, c0 = (idx & 31) * 4;
            BsT[buf][c0 + 0][k] = f2tf32(rb[t].x);
            BsT[buf][c0 + 1][k] = f2tf32(rb[t].y);
            BsT[buf][c0 + 2][k] = f2tf32(rb[t].z);
            BsT[buf][c0 + 3][k] = f2tf32(rb[t].w);
        }
    };

    const int NC = KT / 16;
    loadG(0);
    stage(0);
    __syncthreads();

    for (int ch = 0; ch < NC; ch++) {
        int buf = ch & 1;
        if (ch + 1 < NC) loadG((ch + 1) * 16);
#pragma unroll
        for (int ks = 0; ks < 2; ks++) {
            uint32_t a[2][4];
#pragma unroll
            for (int mt = 0; mt < 2; mt++) {
                int r = wm * 32 + mt * 16 + quad;
                a[mt][0] = As[buf][r][ks * 8 + kq];
                a[mt][1] = As[buf][r + 8][ks * 8 + kq];
                a[mt][2] = As[buf][r][ks * 8 + kq + 4];
                a[mt][3] = As[buf][r + 8][ks * 8 + kq + 4];
            }
#pragma unroll
            for (int nt = 0; nt < 8; nt++) {
                int cb = wn * 64 + nt * 8 + quad;
                uint32_t b0 = BsT[buf][cb][ks * 8 + kq];
                uint32_t b1 = BsT[buf][cb][ks * 8 + kq + 4];
                mma_tf32(c[0][nt], a[0], b0, b1);
                mma_tf32(c[1][nt], a[1], b0, b1);
            }
        }
        if (ch + 1 < NC) stage(buf ^ 1);
        __syncthreads();
    }

#pragma unroll
    for (int mt = 0; mt < 2; mt++) {
#pragma unroll
        for (int nt = 0; nt < 8; nt++) {
            int r0 = brow + wm * 32 + mt * 16 + quad;
            int col = wn * 64 + nt * 8 + kq * 2;
            float2 lo = make_float2(c[mt][nt][0], c[mt][nt][1]);
            float2 hi = make_float2(c[mt][nt][2], c[mt][nt][3]);
            if (OUTHALF) {
                __half* out16 = (__half*)outv;
                if (r0 < M)
                    *(__half2*)(out16 + (size_t)r0 * 128 + col) = __float22half2_rn(lo);
                if (r0 + 8 < M)
                    *(__half2*)(out16 + (size_t)(r0 + 8) * 128 + col) = __float22half2_rn(hi);
            } else if (!SPLIT) {
                float* out = (float*)outv;
                if (r0 < M)     *(float2*)(out + (size_t)r0 * 128 + col) = lo;
                if (r0 + 8 < M) *(float2*)(out + (size_t)(r0 + 8) * 128 + col) = hi;
            } else {
                float* out = (float*)outv;
                const float* bs = wn ? bias2 : bias1;
                int chn = col - wn * 64;
                float bx = bs[chn], by = bs[chn + 1];
                size_t base = wn ? (size_t)M * 64 : 0;
                lo.x += bx; lo.y += by; hi.x += bx; hi.y += by;
                if (r0 < M)     *(float2*)(out + base + (size_t)r0 * 64 + chn) = lo;
                if (r0 + 8 < M) *(float2*)(out + base + (size_t)(r0 + 8) * 64 + chn) = hi;
            }
        }
    }
}

// ---------------------------------------------------------------------------
// CSR aggregation: half-warp (16 lanes) per dst node, 2 nodes per warp.
// One uint4 (8 halves) per lane per gathered row. fp32 accumulate, fp16 out.
template<bool RELU>
__global__ __launch_bounds__(256) void k_agg(
    const int* __restrict__ esrc, const int* __restrict__ off,
    const int* __restrict__ cnt, const float* __restrict__ dinv,
    const float* __restrict__ bias,
    const __half* __restrict__ Hin, __half* __restrict__ Hout, int M)
{
    int node = (blockIdx.x * blockDim.x + threadIdx.x) >> 4;
    int lane = threadIdx.x & 15;
    unsigned mask = 0xFFFFu << (threadIdx.x & 16);
    if (node >= M) return;

    float di = dinv[node];
    float d2 = di * di;

    uint4 raw = *((const uint4*)(Hin + (size_t)node * 128) + lane);
    float2 s0 = __half22float2(*(__half2*)&raw.x);
    float2 s1 = __half22float2(*(__half2*)&raw.y);
    float2 s2 = __half22float2(*(__half2*)&raw.z);
    float2 s3 = __half22float2(*(__half2*)&raw.w);
    float a0 = s0.x * d2, a1 = s0.y * d2, a2 = s1.x * d2, a3 = s1.y * d2;
    float a4 = s2.x * d2, a5 = s2.y * d2, a6 = s3.x * d2, a7 = s3.y * d2;

    int o = off[node], c = cnt[node];
    for (int base = 0; base < c; base += 16) {
        int rem = c - base;
        int lim = rem < 16 ? rem : 16;
        int sv = 0; float dv = 0.f;
        if (lane < lim) { sv = esrc[o + base + lane]; dv = dinv[sv]; }
        for (int j = 0; j < lim; j++) {
            int s = __shfl_sync(mask, sv, j, 16);
            float cf = __shfl_sync(mask, dv, j, 16) * di;
            uint4 r = *((const uint4*)(Hin + (size_t)s * 128) + lane);
            float2 v0 = __half22float2(*(__half2*)&r.x);
            float2 v1 = __half22float2(*(__half2*)&r.y);
            float2 v2 = __half22float2(*(__half2*)&r.z);
            float2 v3 = __half22float2(*(__half2*)&r.w);
            a0 = fmaf(v0.x, cf, a0); a1 = fmaf(v0.y, cf, a1);
            a2 = fmaf(v1.x, cf, a2); a3 = fmaf(v1.y, cf, a3);
            a4 = fmaf(v2.x, cf, a4); a5 = fmaf(v2.y, cf, a5);
            a6 = fmaf(v3.x, cf, a6); a7 = fmaf(v3.y, cf, a7);
        }
    }
    if (RELU) {
        float4 b0 = *((const float4*)bias + lane * 2);
        float4 b1 = *((const float4*)bias + lane * 2 + 1);
        a0 = fmaxf(a0 + b0.x, 0.f); a1 = fmaxf(a1 + b0.y, 0.f);
        a2 = fmaxf(a2 + b0.z, 0.f); a3 = fmaxf(a3 + b0.w, 0.f);
        a4 = fmaxf(a4 + b1.x, 0.f); a5 = fmaxf(a5 + b1.y, 0.f);
        a6 = fmaxf(a6 + b1.z, 0.f); a7 = fmaxf(a7 + b1.w, 0.f);
    }
    uint4 w;
    *(__half2*)&w.x = __float22half2_rn(make_float2(a0, a1));
    *(__half2*)&w.y = __float22half2_rn(make_float2(a2, a3));
    *(__half2*)&w.z = __float22half2_rn(make_float2(a4, a5));
    *(__half2*)&w.w = __float22half2_rn(make_float2(a6, a7));
    *((uint4*)(Hout + (size_t)node * 128) + lane) = w;
}

// ---------------------------------------------------------------------------
extern "C" void kernel_launch(void* const* d_in, const int* in_sizes, int n_in,
                              void* d_out, int out_size)
{
    const float *x = nullptr, *w1 = nullptr, *b1 = nullptr;
    const float *w2 = nullptr, *b2 = nullptr, *w3 = nullptr, *b3 = nullptr;
    const void* ei = nullptr;
    int M = 0, E = 0;

    for (int i = 0; i < n_in; i++) {
        int sz = in_sizes[i];
        if (sz == F_IN * H1) {
            w1 = (const float*)d_in[i];
        } else if (sz == H1) {
            b1 = (const float*)d_in[i];
        } else if (sz == H1 * H2) {
            if (!w2) w2 = (const float*)d_in[i];
            else     w3 = (const float*)d_in[i];
        } else if (sz == H2) {
            if (!b2) b2 = (const float*)d_in[i];
            else     b3 = (const float*)d_in[i];
        } else if (sz < 8000000) {
            ei = d_in[i];
            E = sz / 2;
        } else {
            x = (const float*)d_in[i];
            M = sz / F_IN;
        }
    }

    float *dinv, *H, *AGG;
    int *cnt, *off, *cur, *esrc;
    cudaGetSymbolAddress((void**)&dinv, g_dinv);
    cudaGetSymbolAddress((void**)&H,    g_h);
    cudaGetSymbolAddress((void**)&AGG,  g_agg);
    cudaGetSymbolAddress((void**)&cnt,  g_cnt);
    cudaGetSymbolAddress((void**)&off,  g_off);
    cudaGetSymbolAddress((void**)&cur,  g_cur);
    cudaGetSymbolAddress((void**)&esrc, g_esrc);

    float* out = (float*)d_out;
    __half* H16   = (__half*)H;     // h1 fp16, then agg2 fp16 (g_h)
    __half* HID16 = (__half*)AGG;   // hidden fp16 (g_agg)

    k_init<<<(M + 255) / 256, 256>>>((const int*)ei, 2 * E, cnt, M);
    k_hist<<<(E + 255) / 256, 256>>>(ei, cnt, E, M);
    k_off<<<(M + 255) / 256, 256>>>(cnt, off, cur, dinv, M);
    k_fill<<<(E + 255) / 256, 256>>>(ei, cur, esrc, E, M);

    int gblocks = (M + 127) / 128;
    int ablocks = (M * 16 + 255) / 256;

    // layer 1: x@w1 -> H16 (fp16)
    k_gemm_tc<F_IN, false, true, false><<<gblocks, 256>>>(
        x, w1, nullptr, nullptr, nullptr, H16, M);
    // agg + b1 + relu -> HID16 (fp16)
    k_agg<true><<<ablocks, 256>>>(esrc, off, cnt, dinv, b1, H16, HID16, M);
    // layer-2 aggregation: HID16 -> H16 (fp16, reuse g_h)
    k_agg<false><<<ablocks, 256>>>(esrc, off, cnt, dinv, nullptr, HID16, H16, M);
    // fused output GEMM (fp16 A): H16 @ [w2|w3] + [b2|b3] -> (mu, logvar)
    k_gemm_tc<H1, true, false, true><<<gblocks, 256>>>(
        H16, w2, w3, b2, b3, out, M);
    (void)out_size;
}